// round 13
// baseline (speedup 1.0000x reference)
#include <cuda_runtime.h>
#include <cuda_bf16.h>
#include <math.h>
#include <stdint.h>

#define B 8
#define L 2048
#define D 64
#define BL (B*L)

// ---- k_compute dynamic smem layout (bytes) ----
#define SM_Q   0                       // 64 x 144
#define SM_K0  9216
#define SM_K1  27648
#define SM_V0  46080
#define SM_V1  64512                   // each 128 x 144 = 18432
#define SM_Z   82944                   // 128 floats
#define SM_IZ  83456                   // 64 floats
#define SM_VS  83712                   // 64 floats
#define SM_TOT 83968
// avred (4 strips x 16 x 64 floats = 16 KB) aliases SM_K0 after the main loop.

// ---------------- device scratch ----------------
__device__ __nv_bfloat16 g_qn[BL * D];
__device__ __nv_bfloat16 g_kn[BL * D];
__device__ __nv_bfloat16 g_vb[BL * D];
__device__ float g_vsum[B * D];
__device__ float g_logZ[BL];
__device__ float g_invZ[BL];
// t scratch in mma-tile layout: [1024 rowtiles][128 ktiles][32 lanes] uint4 = 64 MB
__device__ uint4 g_t[1024 * 128 * 32];

// ---------------- PTX helpers ----------------
static __device__ __forceinline__ uint32_t smem_u32(const void* p) {
    return (uint32_t)__cvta_generic_to_shared(p);
}
static __device__ __forceinline__ void ldmat_x4(uint32_t& r0, uint32_t& r1, uint32_t& r2, uint32_t& r3, uint32_t addr) {
    asm volatile("ldmatrix.sync.aligned.m8n8.x4.shared.b16 {%0,%1,%2,%3}, [%4];"
                 : "=r"(r0), "=r"(r1), "=r"(r2), "=r"(r3) : "r"(addr));
}
static __device__ __forceinline__ void ldmat_x4_t(uint32_t& r0, uint32_t& r1, uint32_t& r2, uint32_t& r3, uint32_t addr) {
    asm volatile("ldmatrix.sync.aligned.m8n8.x4.trans.shared.b16 {%0,%1,%2,%3}, [%4];"
                 : "=r"(r0), "=r"(r1), "=r"(r2), "=r"(r3) : "r"(addr));
}
static __device__ __forceinline__ void mma_bf16(float& c0, float& c1, float& c2, float& c3,
    uint32_t a0, uint32_t a1, uint32_t a2, uint32_t a3, uint32_t b0, uint32_t b1) {
    asm volatile("mma.sync.aligned.m16n8k16.row.col.f32.bf16.bf16.f32 "
                 "{%0,%1,%2,%3}, {%4,%5,%6,%7}, {%8,%9}, {%0,%1,%2,%3};"
                 : "+f"(c0), "+f"(c1), "+f"(c2), "+f"(c3)
                 : "r"(a0), "r"(a1), "r"(a2), "r"(a3), "r"(b0), "r"(b1));
}
static __device__ __forceinline__ uint32_t pack2(float lo, float hi) {
    __nv_bfloat162 h = __floats2bfloat162_rn(lo, hi);
    return *reinterpret_cast<uint32_t*>(&h);
}
static __device__ __forceinline__ void cp16(uint32_t dst, const void* src) {
    asm volatile("cp.async.ca.shared.global [%0], [%1], 16;" :: "r"(dst), "l"(src));
}
static __device__ __forceinline__ void cp_commit() {
    asm volatile("cp.async.commit_group;" ::: "memory");
}
static __device__ __forceinline__ void cp_wait1() {
    asm volatile("cp.async.wait_group 1;" ::: "memory");
}
static __device__ __forceinline__ void cp_wait0() {
    asm volatile("cp.async.wait_group 0;" ::: "memory");
}
// e^s - 1 for |s| <= 0.042: cubic Taylor, abs err <= 1.1e-7.
static __device__ __forceinline__ float expm1s(float s) {
    float u = fmaf(s, 0.166666667f, 0.5f);
    u = fmaf(s, u, 1.0f);
    return s * u;
}
// log(1+t) for |t| <= 0.043: cubic, abs err <= 9e-7.
static __device__ __forceinline__ float log1ps(float t) {
    float u = fmaf(t, 0.333333333f, -0.5f);
    u = fmaf(t, u, 1.0f);
    return t * u;
}

// ---------------- K0: zero vsum ----------------
__global__ void k_zero() {
    int i = threadIdx.x;
    if (i < B * D) g_vsum[i] = 0.0f;
}

// ---------------- K1a: l2-normalize q,k -> bf16 ----------------
__global__ void k_prep_qk(const float* __restrict__ q, const float* __restrict__ k) {
    const int w = threadIdx.x >> 5, lane = threadIdx.x & 31;
    const long row = (long)blockIdx.x * 8 + w;
    const float* src;
    __nv_bfloat16* dst;
    long r;
    if (row < BL) { src = q; dst = g_qn; r = row; }
    else          { src = k; dst = g_kn; r = row - BL; }
    float2 x = *(const float2*)&src[r * 64 + lane * 2];
    float ss = x.x * x.x + x.y * x.y;
#pragma unroll
    for (int o = 16; o; o >>= 1) ss += __shfl_xor_sync(0xFFFFFFFFu, ss, o);
    float inv = 1.0f / fmaxf(sqrtf(ss), 1e-12f);
    __nv_bfloat162 h = __floats2bfloat162_rn(x.x * inv, x.y * inv);
    *(__nv_bfloat162*)&dst[r * 64 + lane * 2] = h;
}

// ---------------- K1b: v -> bf16 and per-batch column sums ----------------
__global__ void k_prep_v(const float* __restrict__ v) {
    __shared__ float red[4][64];
    const int t = threadIdx.x;
    const int d = t & 63, g = t >> 6;
    const long base = (long)blockIdx.x * 64;
    const int b = (int)(base >> 11);
    float s = 0.0f;
#pragma unroll
    for (int i = 0; i < 16; i++) {
        long r = base + g + 4 * i;
        float x = v[r * 64 + d];
        s += x;
        g_vb[r * 64 + d] = __float2bfloat16_rn(x);
    }
    red[g][d] = s;
    __syncthreads();
    if (t < 64) {
        float tot = red[0][t] + red[1][t] + red[2][t] + red[3][t];
        atomicAdd(&g_vsum[b * 64 + t], tot);
    }
}

// ---------------- K2: compute kernel ----------------
// CTA = 64 q rows x full K. grid (32,8) = 256 CTAs, 2 CTAs/SM.
// Warps: strip = w&3 (16 q rows), nhalf = w>>2 (nt2 subset of each 128-k chunk).
// Per nt2: QK mma -> s -> t; store t tile (bf16, fragment layout, 1 coalesced STG.128);
// accumulate Z partial + AV partial. Epilogue: combine Z & AV, write out/logZ/invZ.
__global__ void __launch_bounds__(256, 2) k_compute(float* __restrict__ out) {
    extern __shared__ __align__(16) char smem[];
    const uint32_t sbase = smem_u32(smem);
    const int t = threadIdx.x, w = t >> 5, lane = t & 31;
    const int strip = w & 3, nhalf = w >> 2;
    const int qt = blockIdx.x, b = blockIdx.y;
    const int r = lane >> 2, c2 = (lane & 3) * 2;
    const float scale = 0.04f;

    const __nv_bfloat16* qg = g_qn + ((long)b * L + qt * 64) * 64;
    const __nv_bfloat16* kg = g_kn + (long)b * L * 64;
    const __nv_bfloat16* vg = g_vb + (long)b * L * 64;

    float* smemZ = (float*)(smem + SM_Z);
    float* izS   = (float*)(smem + SM_IZ);
    float* vsumS = (float*)(smem + SM_VS);
    if (t < 64) vsumS[t] = g_vsum[b * 64 + t];

    // prefetch chunk 0
#pragma unroll
    for (int i = 0; i < 4; i++) {
        int f = t + 256 * i;
        int row = f >> 3, c = f & 7;
        uint32_t o = row * 144 + c * 16;
        long so = (long)row * 64 + c * 8;
        cp16(sbase + SM_K0 + o, kg + so);
        cp16(sbase + SM_V0 + o, vg + so);
    }
    cp_commit();

    // q tile 64x64 -> smem
#pragma unroll
    for (int i = 0; i < 2; i++) {
        int f = t + 256 * i;
        int row = f >> 3, c = f & 7;
        *(uint4*)(smem + SM_Q + row * 144 + c * 16) = *(const uint4*)&qg[row * 64 + c * 8];
    }
    __syncthreads();
    uint32_t A[4][4];
#pragma unroll
    for (int ksi = 0; ksi < 4; ksi++) {
        uint32_t addr = sbase + SM_Q + (strip * 16 + (lane & 15)) * 144
                      + (ksi * 16 + ((lane >> 4) << 3)) * 2;
        ldmat_x4(A[ksi][0], A[ksi][1], A[ksi][2], A[ksi][3], addr);
    }

    // t scratch base for this warp's row-tile
    const int rowtile = b * 128 + qt * 4 + strip;
    uint4* tg = g_t + ((long)rowtile * 128) * 32 + lane;

    float acc[8][4];
#pragma unroll
    for (int i = 0; i < 8; i++)
#pragma unroll
        for (int j = 0; j < 4; j++) acc[i][j] = 0.0f;
    float tsumA = 0.0f, tsumB = 0.0f;

    for (int kc = 0; kc < 16; kc++) {
        const uint32_t kbuf = (kc & 1) ? SM_K1 : SM_K0;
        const uint32_t vbuf = (kc & 1) ? SM_V1 : SM_V0;
        if (kc < 15) {
            const uint32_t kn = (kc & 1) ? SM_K0 : SM_K1;
            const uint32_t vn = (kc & 1) ? SM_V0 : SM_V1;
            const __nv_bfloat16* ks = kg + (long)(kc + 1) * 128 * 64;
            const __nv_bfloat16* vs = vg + (long)(kc + 1) * 128 * 64;
#pragma unroll
            for (int i = 0; i < 4; i++) {
                int f = t + 256 * i;
                int row = f >> 3, c = f & 7;
                uint32_t o = row * 144 + c * 16;
                long so = (long)row * 64 + c * 8;
                cp16(sbase + kn + o, ks + so);
                cp16(sbase + vn + o, vs + so);
            }
            cp_commit();
            cp_wait1();
        } else {
            cp_wait0();
        }
        __syncthreads();

#pragma unroll
        for (int nt2l = 0; nt2l < 4; nt2l++) {
            const int nt2 = nhalf * 4 + nt2l;
            float cf[2][4] = {{0.f,0.f,0.f,0.f},{0.f,0.f,0.f,0.f}};
#pragma unroll
            for (int ksi = 0; ksi < 4; ksi++) {
                uint32_t b0, b1, b2, b3;
                uint32_t addr = sbase + kbuf
                    + (nt2 * 16 + ((lane >> 4) << 3) + (lane & 7)) * 144
                    + (ksi * 16 + (((lane >> 3) & 1) << 3)) * 2;
                ldmat_x4(b0, b1, b2, b3, addr);
                mma_bf16(cf[0][0], cf[0][1], cf[0][2], cf[0][3], A[ksi][0], A[ksi][1], A[ksi][2], A[ksi][3], b0, b1);
                mma_bf16(cf[1][0], cf[1][1], cf[1][2], cf[1][3], A[ksi][0], A[ksi][1], A[ksi][2], A[ksi][3], b2, b3);
            }
            float t00 = expm1s(cf[0][0] * scale), t01 = expm1s(cf[0][1] * scale); // row r,   cols c2
            float t10 = expm1s(cf[0][2] * scale), t11 = expm1s(cf[0][3] * scale); // row r+8, cols c2
            float t20 = expm1s(cf[1][0] * scale), t21 = expm1s(cf[1][1] * scale); // row r,   cols c2+8
            float t30 = expm1s(cf[1][2] * scale), t31 = expm1s(cf[1][3] * scale); // row r+8, cols c2+8
            tsumA += t00 + t01 + t20 + t21;
            tsumB += t10 + t11 + t30 + t31;
            uint32_t a0 = pack2(t00, t01);
            uint32_t a1 = pack2(t10, t11);
            uint32_t a2 = pack2(t20, t21);
            uint32_t a3 = pack2(t30, t31);
            // coalesced tile store: 32 lanes x 16B = 512B
            uint4 tv; tv.x = a0; tv.y = a1; tv.z = a2; tv.w = a3;
            __stcs((int4*)&tg[(kc * 8 + nt2) * 32], *(int4*)&tv);
            // AV mma
#pragma unroll
            for (int nn2 = 0; nn2 < 4; nn2++) {
                uint32_t b0, b1, b2, b3;
                uint32_t addr = sbase + vbuf
                    + (nt2 * 16 + (((lane >> 3) & 1) << 3) + (lane & 7)) * 144
                    + (nn2 * 16 + ((lane >> 4) << 3)) * 2;
                ldmat_x4_t(b0, b1, b2, b3, addr);
                mma_bf16(acc[2 * nn2][0], acc[2 * nn2][1], acc[2 * nn2][2], acc[2 * nn2][3],
                         a0, a1, a2, a3, b0, b1);
                mma_bf16(acc[2 * nn2 + 1][0], acc[2 * nn2 + 1][1], acc[2 * nn2 + 1][2], acc[2 * nn2 + 1][3],
                         a0, a1, a2, a3, b2, b3);
            }
        }
        __syncthreads();
    }

    // ---- epilogue ----
    tsumA += __shfl_xor_sync(0xFFFFFFFFu, tsumA, 1);
    tsumA += __shfl_xor_sync(0xFFFFFFFFu, tsumA, 2);
    tsumB += __shfl_xor_sync(0xFFFFFFFFu, tsumB, 1);
    tsumB += __shfl_xor_sync(0xFFFFFFFFu, tsumB, 2);
    if ((lane & 3) == 0) {
        smemZ[nhalf * 64 + strip * 16 + r]     = tsumA;
        smemZ[nhalf * 64 + strip * 16 + r + 8] = tsumB;
    }
    float* avred = (float*)(smem + SM_K0) + strip * 1024;   // k-buffers are dead
    if (nhalf == 1) {
#pragma unroll
        for (int nt = 0; nt < 8; nt++) {
            avred[r * 64 + nt * 8 + c2]           = acc[nt][0];
            avred[r * 64 + nt * 8 + c2 + 1]       = acc[nt][1];
            avred[(r + 8) * 64 + nt * 8 + c2]     = acc[nt][2];
            avred[(r + 8) * 64 + nt * 8 + c2 + 1] = acc[nt][3];
        }
    }
    __syncthreads();
    const long growCTA = (long)b * L + qt * 64;
    if (t < 64) {
        float z = 2048.0f + smemZ[t] + smemZ[64 + t];
        float iz = 1.0f / z;
        izS[t] = iz;
        g_invZ[growCTA + t] = iz;
        g_logZ[growCTA + t] = logf(z);
    }
    __syncthreads();
    if (nhalf == 0) {
        const float izA = izS[strip * 16 + r];
        const float izB = izS[strip * 16 + r + 8];
        float* oA = out + (growCTA + strip * 16 + r) * 64;
        float* oB = out + (growCTA + strip * 16 + 8 + r) * 64;
#pragma unroll
        for (int nt = 0; nt < 8; nt++) {
            float p0 = acc[nt][0] + avred[r * 64 + nt * 8 + c2];
            float p1 = acc[nt][1] + avred[r * 64 + nt * 8 + c2 + 1];
            float p2 = acc[nt][2] + avred[(r + 8) * 64 + nt * 8 + c2];
            float p3 = acc[nt][3] + avred[(r + 8) * 64 + nt * 8 + c2 + 1];
            float vs0 = vsumS[nt * 8 + c2];
            float vs1 = vsumS[nt * 8 + c2 + 1];
            *(float2*)&oA[nt * 8 + c2] = make_float2((vs0 + p0) * izA, (vs1 + p1) * izA);
            *(float2*)&oB[nt * 8 + c2] = make_float2((vs0 + p2) * izB, (vs1 + p3) * izB);
        }
    }
}

// ---------------- K3: streaming softmax writer ----------------
// grid 1024 CTAs (one 16-row band each), 256 threads. Reads t tiles through smem,
// writes attn = fma(t,iz,iz), lattn = log1p(t) - lz, fully coalesced.
__global__ void __launch_bounds__(256) k_soft(float* __restrict__ attn,
                                              float* __restrict__ lattn) {
    __shared__ __align__(16) char buf[2][8 * 544];   // 8 tiles, 544B padded slots
    __shared__ float izS[16], lzS[16];
    const int t = threadIdx.x;
    const int ct = blockIdx.x;
    const long grow = (long)ct * 16;

    if (t < 16) {
        izS[t] = g_invZ[grow + t];
        lzS[t] = g_logZ[grow + t];
    }

    const char* tgb = (const char*)(g_t + (long)ct * 128 * 32);
    const uint32_t b0addr = smem_u32(&buf[0][0]);
    const uint32_t b1addr = smem_u32(&buf[1][0]);
    const uint32_t dsto = (t >> 5) * 544 + (t & 31) * 16;
    const long srco = (long)(t >> 5) * 512 + (t & 31) * 16;

    // prefetch chunk 0
    cp16(b0addr + dsto, tgb + srco);
    cp_commit();

    const int row16 = t >> 4, cg = t & 15;
    const int j = cg >> 1, base = (cg & 1) * 8;
    const int part = ((row16 >> 3) & 1) | ((cg & 1) << 1);
    const int wbase = j * 136 + ((row16 & 7) << 4) + part;
    const float iz = izS[0];  // placeholder to keep compiler from reordering before sync
    (void)iz;

    for (int cc = 0; cc < 16; cc++) {
        if (cc < 15) {
            uint32_t dst = ((cc + 1) & 1) ? b1addr : b0addr;
            cp16(dst + dsto, tgb + (long)(cc + 1) * 8 * 512 + srco);
            cp_commit();
            cp_wait1();
        } else {
            cp_wait0();
        }
        __syncthreads();

        const uint32_t* wb = (const uint32_t*)&buf[cc & 1][0];
        uint32_t w0 = wb[wbase];
        uint32_t w1 = wb[wbase + 4];
        uint32_t w2 = wb[wbase + 8];
        uint32_t w3 = wb[wbase + 12];
        float2 p0 = __bfloat1622float2(*(__nv_bfloat162*)&w0);
        float2 p1 = __bfloat1622float2(*(__nv_bfloat162*)&w1);
        float2 p2 = __bfloat1622float2(*(__nv_bfloat162*)&w2);
        float2 p3 = __bfloat1622float2(*(__nv_bfloat162*)&w3);

        const float izr = izS[row16], lzr = lzS[row16];
        const long off = grow * L + (long)row16 * L + cc * 128 + j * 16 + base;
        __stcs((float4*)&attn[off],
               make_float4(fmaf(p0.x, izr, izr), fmaf(p0.y, izr, izr),
                           fmaf(p1.x, izr, izr), fmaf(p1.y, izr, izr)));
        __stcs((float4*)&attn[off + 4],
               make_float4(fmaf(p2.x, izr, izr), fmaf(p2.y, izr, izr),
                           fmaf(p3.x, izr, izr), fmaf(p3.y, izr, izr)));
        __stcs((float4*)&lattn[off],
               make_float4(log1ps(p0.x) - lzr, log1ps(p0.y) - lzr,
                           log1ps(p1.x) - lzr, log1ps(p1.y) - lzr));
        __stcs((float4*)&lattn[off + 4],
               make_float4(log1ps(p2.x) - lzr, log1ps(p2.y) - lzr,
                           log1ps(p3.x) - lzr, log1ps(p3.y) - lzr));
        __syncthreads();
    }
}

// ---------------- launcher ----------------
extern "C" void kernel_launch(void* const* d_in, const int* in_sizes, int n_in,
                              void* d_out, int out_size) {
    const float* q = (const float*)d_in[0];
    const float* k = (const float*)d_in[1];
    const float* v = (const float*)d_in[2];

    float* out   = (float*)d_out;
    float* attn  = out + (long)BL * 64;
    float* lattn = attn + (long)BL * L;

    static int smem_set = 0;
    if (!smem_set) {
        cudaFuncSetAttribute(k_compute, cudaFuncAttributeMaxDynamicSharedMemorySize, SM_TOT);
        smem_set = 1;
    }

    k_zero<<<1, 512>>>();
    k_prep_qk<<<2 * BL / 8, 256>>>(q, k);
    k_prep_v<<<BL / 64, 256>>>(v);

    dim3 gc(32, B);                           // 256 CTAs
    k_compute<<<gc, 256, SM_TOT>>>(out);

    k_soft<<<1024, 256>>>(attn, lattn);
}

// round 14
// speedup vs baseline: 1.2927x; 1.2927x over previous
#include <cuda_runtime.h>
#include <cuda_bf16.h>
#include <math.h>
#include <stdint.h>

#define B 8
#define L 2048
#define D 64
#define BL (B*L)

// ---- k_main dynamic smem layout (bytes) ----
#define SM_Q   0                       // 64 x 144
#define SM_K0  9216
#define SM_K1  27648
#define SM_V0  46080
#define SM_V1  64512                   // each 128 x 144 = 18432
#define SM_VS  82944                   // 64 floats -> 256B
#define SM_ST  83200                   // 8 warps x 1152
#define SM_WST 1152                    // tS 1024 + lz 64 + iz 64
#define SM_TOT (SM_ST + 8 * SM_WST)    // 92416  -> 2 CTAs/SM
// avred (4 strips x 1024 floats = 16 KB) aliases SM_K0 after the main loop.

// ---------------- device scratch ----------------
__device__ __nv_bfloat16 g_qn[BL * D];
__device__ __nv_bfloat16 g_kn[BL * D];
__device__ __nv_bfloat16 g_vb[BL * D];
__device__ float g_vsum[B * D];
__device__ float g_ksum[B * D];
__device__ float g_M[B * D * D];
__device__ float g_logZ[BL];
__device__ float g_invZ[BL];

// ---------------- PTX helpers ----------------
static __device__ __forceinline__ uint32_t smem_u32(const void* p) {
    return (uint32_t)__cvta_generic_to_shared(p);
}
static __device__ __forceinline__ void ldmat_x4(uint32_t& r0, uint32_t& r1, uint32_t& r2, uint32_t& r3, uint32_t addr) {
    asm volatile("ldmatrix.sync.aligned.m8n8.x4.shared.b16 {%0,%1,%2,%3}, [%4];"
                 : "=r"(r0), "=r"(r1), "=r"(r2), "=r"(r3) : "r"(addr));
}
static __device__ __forceinline__ void ldmat_x4_t(uint32_t& r0, uint32_t& r1, uint32_t& r2, uint32_t& r3, uint32_t addr) {
    asm volatile("ldmatrix.sync.aligned.m8n8.x4.trans.shared.b16 {%0,%1,%2,%3}, [%4];"
                 : "=r"(r0), "=r"(r1), "=r"(r2), "=r"(r3) : "r"(addr));
}
static __device__ __forceinline__ void mma_bf16(float& c0, float& c1, float& c2, float& c3,
    uint32_t a0, uint32_t a1, uint32_t a2, uint32_t a3, uint32_t b0, uint32_t b1) {
    asm volatile("mma.sync.aligned.m16n8k16.row.col.f32.bf16.bf16.f32 "
                 "{%0,%1,%2,%3}, {%4,%5,%6,%7}, {%8,%9}, {%0,%1,%2,%3};"
                 : "+f"(c0), "+f"(c1), "+f"(c2), "+f"(c3)
                 : "r"(a0), "r"(a1), "r"(a2), "r"(a3), "r"(b0), "r"(b1));
}
static __device__ __forceinline__ uint32_t pack2(float lo, float hi) {
    __nv_bfloat162 h = __floats2bfloat162_rn(lo, hi);
    return *reinterpret_cast<uint32_t*>(&h);
}
static __device__ __forceinline__ void cp16(uint32_t dst, const void* src) {
    asm volatile("cp.async.ca.shared.global [%0], [%1], 16;" :: "r"(dst), "l"(src));
}
static __device__ __forceinline__ void cp_commit() {
    asm volatile("cp.async.commit_group;" ::: "memory");
}
static __device__ __forceinline__ void cp_wait1() {
    asm volatile("cp.async.wait_group 1;" ::: "memory");
}
static __device__ __forceinline__ void cp_wait0() {
    asm volatile("cp.async.wait_group 0;" ::: "memory");
}
// e^s - 1 for |s| <= 0.042: cubic Taylor, abs err <= 1.1e-7.
static __device__ __forceinline__ float expm1s(float s) {
    float u = fmaf(s, 0.166666667f, 0.5f);
    u = fmaf(s, u, 1.0f);
    return s * u;
}
// log(1+t) for |t| <= 0.043: cubic, abs err <= 9e-7.
static __device__ __forceinline__ float log1ps(float t) {
    float u = fmaf(t, 0.333333333f, -0.5f);
    u = fmaf(t, u, 1.0f);
    return t * u;
}

// ---------------- K0: zero accumulators ----------------
__global__ void k_zero() {
    int i = blockIdx.x * 256 + threadIdx.x;
    if (i < B * D * D) g_M[i] = 0.0f;
    if (i < B * D) { g_ksum[i] = 0.0f; g_vsum[i] = 0.0f; }
}

// ---------------- K1a: l2-normalize q,k -> bf16 ----------------
__global__ void k_prep_qk(const float* __restrict__ q, const float* __restrict__ k) {
    const int w = threadIdx.x >> 5, lane = threadIdx.x & 31;
    const long row = (long)blockIdx.x * 8 + w;
    const float* src;
    __nv_bfloat16* dst;
    long r;
    if (row < BL) { src = q; dst = g_qn; r = row; }
    else          { src = k; dst = g_kn; r = row - BL; }
    float2 x = *(const float2*)&src[r * 64 + lane * 2];
    float ss = x.x * x.x + x.y * x.y;
#pragma unroll
    for (int o = 16; o; o >>= 1) ss += __shfl_xor_sync(0xFFFFFFFFu, ss, o);
    float inv = 1.0f / fmaxf(sqrtf(ss), 1e-12f);
    __nv_bfloat162 h = __floats2bfloat162_rn(x.x * inv, x.y * inv);
    *(__nv_bfloat162*)&dst[r * 64 + lane * 2] = h;
}

// ---------------- K1b: v -> bf16 and per-batch column sums ----------------
__global__ void k_prep_v(const float* __restrict__ v) {
    __shared__ float red[4][64];
    const int t = threadIdx.x;
    const int d = t & 63, g = t >> 6;
    const long base = (long)blockIdx.x * 64;
    const int b = (int)(base >> 11);
    float s = 0.0f;
#pragma unroll
    for (int i = 0; i < 16; i++) {
        long r = base + g + 4 * i;
        float x = v[r * 64 + d];
        s += x;
        g_vb[r * 64 + d] = __float2bfloat16_rn(x);
    }
    red[g][d] = s;
    __syncthreads();
    if (t < 64) {
        float tot = red[0][t] + red[1][t] + red[2][t] + red[3][t];
        atomicAdd(&g_vsum[b * 64 + t], tot);
    }
}

// ---------------- K1c: ksum per batch (256 CTAs) ----------------
__global__ void k_ksum() {
    __shared__ float red[4][64];
    const int t = threadIdx.x;
    const int ct = blockIdx.x, b = blockIdx.y;
    const int d = t & 63, g = t >> 6;
    const long base = (long)b * L + ct * 64;
    float s = 0.0f;
#pragma unroll
    for (int i = 0; i < 16; i++)
        s += __bfloat162float(g_kn[(base + g + 4 * i) * 64 + d]);
    red[g][d] = s;
    __syncthreads();
    if (t < 64)
        atomicAdd(&g_ksum[b * 64 + t], red[0][t] + red[1][t] + red[2][t] + red[3][t]);
}

// ---------------- K1d: M = khat^T khat via mma (verified round 12) ----------------
__global__ void __launch_bounds__(256) k_moment() {
    __shared__ __align__(16) __nv_bfloat16 km[128][72];
    const int t = threadIdx.x, w = t >> 5, lane = t & 31;
    const int ct = blockIdx.x, b = blockIdx.y;
    const int i0 = (w & 3) * 16, j0 = (w >> 2) * 32;
    const __nv_bfloat16* kg = g_kn + ((long)b * L + ct * 512) * 64;

    float acc[4][4];
#pragma unroll
    for (int i = 0; i < 4; i++)
#pragma unroll
        for (int j = 0; j < 4; j++) acc[i][j] = 0.0f;

    for (int ch = 0; ch < 4; ch++) {
        __syncthreads();
#pragma unroll
        for (int i = 0; i < 4; i++) {
            int f = t + 256 * i;
            int row = f >> 3, c = f & 7;
            *(uint4*)&km[row][c * 8] = *(const uint4*)&kg[(ch * 128 + row) * 64 + c * 8];
        }
        __syncthreads();
#pragma unroll
        for (int ks = 0; ks < 8; ks++) {
            const int krow = ks * 16 + ((lane >> 3) & 1) * 8 + (lane & 7);
            uint32_t p0, p1, p2, p3;
            ldmat_x4_t(p0, p1, p2, p3, smem_u32(&km[krow][i0 + ((lane >> 4) << 3)]));
            uint32_t q0, q1, q2, q3;
            ldmat_x4_t(q0, q1, q2, q3, smem_u32(&km[krow][j0 + ((lane >> 4) << 3)]));
            uint32_t u0, u1, u2, u3;
            ldmat_x4_t(u0, u1, u2, u3, smem_u32(&km[krow][j0 + 16 + ((lane >> 4) << 3)]));
            mma_bf16(acc[0][0], acc[0][1], acc[0][2], acc[0][3], p0, p2, p1, p3, q0, q1);
            mma_bf16(acc[1][0], acc[1][1], acc[1][2], acc[1][3], p0, p2, p1, p3, q2, q3);
            mma_bf16(acc[2][0], acc[2][1], acc[2][2], acc[2][3], p0, p2, p1, p3, u0, u1);
            mma_bf16(acc[3][0], acc[3][1], acc[3][2], acc[3][3], p0, p2, p1, p3, u2, u3);
        }
    }
    float* Mb = g_M + (long)b * 4096;
    const int row = i0 + (lane >> 2);
    const int colb = j0 + (lane & 3) * 2;
#pragma unroll
    for (int jj = 0; jj < 4; jj++) {
        int col = colb + jj * 8;
        atomicAdd(&Mb[row * 64 + col],           acc[jj][0]);
        atomicAdd(&Mb[row * 64 + col + 1],       acc[jj][1]);
        atomicAdd(&Mb[(row + 8) * 64 + col],     acc[jj][2]);
        atomicAdd(&Mb[(row + 8) * 64 + col + 1], acc[jj][3]);
    }
}

// ---------------- K1e: per-row Z via moments ----------------
__global__ void __launch_bounds__(256) k_z() {
    __shared__ float Ms[64][64];
    __shared__ __align__(16) __nv_bfloat16 qs[64][64];
    __shared__ float ksums[64];
    const int t = threadIdx.x;
    const int ct = blockIdx.x, b = blockIdx.y;

    const float* Mg = g_M + (long)b * 4096;
#pragma unroll
    for (int i = 0; i < 4; i++) {
        int f = t + 256 * i;
        *(float4*)&Ms[0][0 + f * 4] = *(const float4*)&Mg[f * 4];
    }
    const __nv_bfloat16* qg = g_qn + ((long)b * L + ct * 64) * 64;
#pragma unroll
    for (int i = 0; i < 2; i++) {
        int f = t + 256 * i;
        int row = f >> 3, c = f & 7;
        *(uint4*)&qs[row][c * 8] = *(const uint4*)&qg[row * 64 + c * 8];
    }
    if (t < 64) ksums[t] = g_ksum[b * 64 + t];
    __syncthreads();

    const int r = t >> 2, j0 = (t & 3) * 16;
    float qj[16];
    {
        const __nv_bfloat162* p = (const __nv_bfloat162*)&qs[r][j0];
#pragma unroll
        for (int j2 = 0; j2 < 8; j2++) {
            float2 f2 = __bfloat1622float2(p[j2]);
            qj[2 * j2] = f2.x; qj[2 * j2 + 1] = f2.y;
        }
    }
    float uj[16];
#pragma unroll
    for (int j = 0; j < 16; j++) uj[j] = 0.0f;
    for (int i = 0; i < 64; i++) {
        float qi = __bfloat162float(qs[r][i]);
#pragma unroll
        for (int j4 = 0; j4 < 4; j4++) {
            float4 m = *(float4*)&Ms[i][j0 + j4 * 4];
            uj[j4 * 4 + 0] = fmaf(qi, m.x, uj[j4 * 4 + 0]);
            uj[j4 * 4 + 1] = fmaf(qi, m.y, uj[j4 * 4 + 1]);
            uj[j4 * 4 + 2] = fmaf(qi, m.z, uj[j4 * 4 + 2]);
            uj[j4 * 4 + 3] = fmaf(qi, m.w, uj[j4 * 4 + 3]);
        }
    }
    float quad = 0.0f, sk = 0.0f;
#pragma unroll
    for (int j = 0; j < 16; j++) {
        quad = fmaf(uj[j], qj[j], quad);
        sk   = fmaf(ksums[j0 + j], qj[j], sk);
    }
    quad += __shfl_xor_sync(0xFFFFFFFFu, quad, 1);
    quad += __shfl_xor_sync(0xFFFFFFFFu, quad, 2);
    sk   += __shfl_xor_sync(0xFFFFFFFFu, sk, 1);
    sk   += __shfl_xor_sync(0xFFFFFFFFu, sk, 2);
    if ((t & 3) == 0) {
        long row = (long)b * L + ct * 64 + r;
        float z = 2048.0f + sk * 0.04f + quad * 0.0008f;
        g_logZ[row] = logf(z);
        g_invZ[row] = 1.0f / z;
    }
}

// ---------------- K2: fused single-pass main ----------------
// CTA = 64 q rows, grid (32,8), 2 CTAs/SM. Warps: strip=w&3, nhalf=w>>2.
// Per nt2: QK mma -> t; stage t (bf16) in warp-private smem; AV mma; every 2nd nt2
// write the 16x32 block of attn & lattn with full-line STG.128.
__global__ void __launch_bounds__(256, 2) k_main(float* __restrict__ attn,
                                                 float* __restrict__ lattn,
                                                 float* __restrict__ out) {
    extern __shared__ __align__(16) char smem[];
    const uint32_t sbase = smem_u32(smem);
    const int t = threadIdx.x, w = t >> 5, lane = t & 31;
    const int strip = w & 3, nhalf = w >> 2;
    const int qt = blockIdx.x, b = blockIdx.y;
    const int r = lane >> 2, c2 = (lane & 3) * 2;
    const float scale = 0.04f;

    const __nv_bfloat16* qg = g_qn + ((long)b * L + qt * 64) * 64;
    const __nv_bfloat16* kg = g_kn + (long)b * L * 64;
    const __nv_bfloat16* vg = g_vb + (long)b * L * 64;

    float* vsumS = (float*)(smem + SM_VS);
    if (t < 64) vsumS[t] = g_vsum[b * 64 + t];

    const long grow0 = (long)b * L + qt * 64 + strip * 16;
    char* stW = smem + SM_ST + w * SM_WST;
    uint32_t* tS = (uint32_t*)stW;          // [16][16]
    float* lzS   = (float*)(stW + 1024);    // [16]
    float* izS   = (float*)(stW + 1088);    // [16]
    if (lane < 16) {
        lzS[lane] = g_logZ[grow0 + lane];
        izS[lane] = g_invZ[grow0 + lane];
    }

    // prefetch chunk 0
#pragma unroll
    for (int i = 0; i < 4; i++) {
        int f = t + 256 * i;
        int row = f >> 3, c = f & 7;
        uint32_t o = row * 144 + c * 16;
        long so = (long)row * 64 + c * 8;
        cp16(sbase + SM_K0 + o, kg + so);
        cp16(sbase + SM_V0 + o, vg + so);
    }
    cp_commit();

    // q tile 64x64 -> smem
#pragma unroll
    for (int i = 0; i < 2; i++) {
        int f = t + 256 * i;
        int row = f >> 3, c = f & 7;
        *(uint4*)(smem + SM_Q + row * 144 + c * 16) = *(const uint4*)&qg[row * 64 + c * 8];
    }
    __syncthreads();
    uint32_t A[4][4];
#pragma unroll
    for (int ksi = 0; ksi < 4; ksi++) {
        uint32_t addr = sbase + SM_Q + (strip * 16 + (lane & 15)) * 144
                      + (ksi * 16 + ((lane >> 4) << 3)) * 2;
        ldmat_x4(A[ksi][0], A[ksi][1], A[ksi][2], A[ksi][3], addr);
    }

    float* aBase = attn + grow0 * L;
    float* lBase = lattn + grow0 * L;

    float acc[8][4];
#pragma unroll
    for (int i = 0; i < 8; i++)
#pragma unroll
        for (int j = 0; j < 4; j++) acc[i][j] = 0.0f;

    for (int kc = 0; kc < 16; kc++) {
        const uint32_t kbuf = (kc & 1) ? SM_K1 : SM_K0;
        const uint32_t vbuf = (kc & 1) ? SM_V1 : SM_V0;
        if (kc < 15) {
            const uint32_t kn = (kc & 1) ? SM_K0 : SM_K1;
            const uint32_t vn = (kc & 1) ? SM_V0 : SM_V1;
            const __nv_bfloat16* ks = kg + (long)(kc + 1) * 128 * 64;
            const __nv_bfloat16* vs = vg + (long)(kc + 1) * 128 * 64;
#pragma unroll
            for (int i = 0; i < 4; i++) {
                int f = t + 256 * i;
                int row = f >> 3, c = f & 7;
                uint32_t o = row * 144 + c * 16;
                long so = (long)row * 64 + c * 8;
                cp16(sbase + kn + o, ks + so);
                cp16(sbase + vn + o, vs + so);
            }
            cp_commit();
            cp_wait1();
        } else {
            cp_wait0();
        }
        __syncthreads();

#pragma unroll
        for (int nt2l = 0; nt2l < 4; nt2l++) {
            const int nt2 = nhalf * 4 + nt2l;
            float cf[2][4] = {{0.f,0.f,0.f,0.f},{0.f,0.f,0.f,0.f}};
#pragma unroll
            for (int ksi = 0; ksi < 4; ksi++) {
                uint32_t b0, b1, b2, b3;
                uint32_t addr = sbase + kbuf
                    + (nt2 * 16 + ((lane >> 4) << 3) + (lane & 7)) * 144
                    + (ksi * 16 + (((lane >> 3) & 1) << 3)) * 2;
                ldmat_x4(b0, b1, b2, b3, addr);
                mma_bf16(cf[0][0], cf[0][1], cf[0][2], cf[0][3], A[ksi][0], A[ksi][1], A[ksi][2], A[ksi][3], b0, b1);
                mma_bf16(cf[1][0], cf[1][1], cf[1][2], cf[1][3], A[ksi][0], A[ksi][1], A[ksi][2], A[ksi][3], b2, b3);
            }
            uint32_t a0 = pack2(expm1s(cf[0][0] * scale), expm1s(cf[0][1] * scale)); // row r, cols c2
            uint32_t a1 = pack2(expm1s(cf[0][2] * scale), expm1s(cf[0][3] * scale)); // row r+8
            uint32_t a2 = pack2(expm1s(cf[1][0] * scale), expm1s(cf[1][1] * scale)); // row r, cols c2+8
            uint32_t a3 = pack2(expm1s(cf[1][2] * scale), expm1s(cf[1][3] * scale)); // row r+8

            // stage t
            const int tcol = (nt2l & 1) * 8 + (c2 >> 1);
            tS[r * 16 + tcol]           = a0;
            tS[(r + 8) * 16 + tcol]     = a1;
            tS[r * 16 + tcol + 4]       = a2;
            tS[(r + 8) * 16 + tcol + 4] = a3;

            // AV mma
#pragma unroll
            for (int nn2 = 0; nn2 < 4; nn2++) {
                uint32_t b0, b1, b2, b3;
                uint32_t addr = sbase + vbuf
                    + (nt2 * 16 + (((lane >> 3) & 1) << 3) + (lane & 7)) * 144
                    + (nn2 * 16 + ((lane >> 4) << 3)) * 2;
                ldmat_x4_t(b0, b1, b2, b3, addr);
                mma_bf16(acc[2 * nn2][0], acc[2 * nn2][1], acc[2 * nn2][2], acc[2 * nn2][3],
                         a0, a1, a2, a3, b0, b1);
                mma_bf16(acc[2 * nn2 + 1][0], acc[2 * nn2 + 1][1], acc[2 * nn2 + 1][2], acc[2 * nn2 + 1][3],
                         a0, a1, a2, a3, b2, b3);
            }

            if (nt2l & 1) {
                __syncwarp();
                const int colbase = kc * 128 + (nt2 - 1) * 16;
                const int col4 = (lane & 7) * 4;
#pragma unroll
                for (int iter = 0; iter < 4; iter++) {
                    const int row16 = iter * 4 + (lane >> 3);
                    const float lz = lzS[row16];
                    const float iz = izS[row16];
                    uint2 tv = *(uint2*)&tS[row16 * 16 + (col4 >> 1)];
                    float2 ta = __bfloat1622float2(*(__nv_bfloat162*)&tv.x);
                    float2 tb = __bfloat1622float2(*(__nv_bfloat162*)&tv.y);
                    const long off = (long)row16 * L + colbase + col4;
                    __stcs((float4*)&aBase[off],
                           make_float4(fmaf(ta.x, iz, iz), fmaf(ta.y, iz, iz),
                                       fmaf(tb.x, iz, iz), fmaf(tb.y, iz, iz)));
                    __stcs((float4*)&lBase[off],
                           make_float4(log1ps(ta.x) - lz, log1ps(ta.y) - lz,
                                       log1ps(tb.x) - lz, log1ps(tb.y) - lz));
                }
                __syncwarp();
            }
        }
        __syncthreads();
    }

    // ---- AV reduction across nhalf + out ----
    float* avred = (float*)(smem + SM_K0) + strip * 1024;   // k-buffers dead
    if (nhalf == 1) {
#pragma unroll
        for (int nt = 0; nt < 8; nt++) {
            avred[r * 64 + nt * 8 + c2]           = acc[nt][0];
            avred[r * 64 + nt * 8 + c2 + 1]       = acc[nt][1];
            avred[(r + 8) * 64 + nt * 8 + c2]     = acc[nt][2];
            avred[(r + 8) * 64 + nt * 8 + c2 + 1] = acc[nt][3];
        }
    }
    __syncthreads();
    if (nhalf == 0) {
        const float izA = izS[r], izB = izS[r + 8];
        float* oA = out + (grow0 + r) * 64;
        float* oB = out + (grow0 + 8 + r) * 64;
#pragma unroll
        for (int nt = 0; nt < 8; nt++) {
            float p0 = acc[nt][0] + avred[r * 64 + nt * 8 + c2];
            float p1 = acc[nt][1] + avred[r * 64 + nt * 8 + c2 + 1];
            float p2 = acc[nt][2] + avred[(r + 8) * 64 + nt * 8 + c2];
            float p3 = acc[nt][3] + avred[(r + 8) * 64 + nt * 8 + c2 + 1];
            float vs0 = vsumS[nt * 8 + c2];
            float vs1 = vsumS[nt * 8 + c2 + 1];
            *(float2*)&oA[nt * 8 + c2] = make_float2((vs0 + p0) * izA, (vs1 + p1) * izA);
            *(float2*)&oB[nt * 8 + c2] = make_float2((vs0 + p2) * izB, (vs1 + p3) * izB);
        }
    }
}

// ---------------- launcher ----------------
extern "C" void kernel_launch(void* const* d_in, const int* in_sizes, int n_in,
                              void* d_out, int out_size) {
    const float* q = (const float*)d_in[0];
    const float* k = (const float*)d_in[1];
    const float* v = (const float*)d_in[2];

    float* out   = (float*)d_out;
    float* attn  = out + (long)BL * 64;
    float* lattn = attn + (long)BL * L;

    static int smem_set = 0;
    if (!smem_set) {
        cudaFuncSetAttribute(k_main, cudaFuncAttributeMaxDynamicSharedMemorySize, SM_TOT);
        smem_set = 1;
    }

    k_zero<<<128, 256>>>();
    k_prep_qk<<<2 * BL / 8, 256>>>(q, k);
    k_prep_v<<<BL / 64, 256>>>(v);

    dim3 gks(32, B);
    k_ksum<<<gks, 256>>>();

    dim3 gm(4, B);
    k_moment<<<gm, 256>>>();

    dim3 gz(32, B);
    k_z<<<gz, 256>>>();

    dim3 g(32, B);                            // 256 CTAs, 2/SM
    k_main<<<g, 256, SM_TOT>>>(attn, lattn, out);
}